// round 12
// baseline (speedup 1.0000x reference)
#include <cuda_runtime.h>
#include <math.h>
#include <cstdint>

#define NP 512
#define TT 12

typedef unsigned long long ull;

// ---------------- f32x2 packed helpers (sm_103a) ------------------------------------
__device__ __forceinline__ ull f32x2_fma(ull a, ull b, ull c){
    ull d;
    asm("fma.rn.f32x2 %0, %1, %2, %3;" : "=l"(d) : "l"(a), "l"(b), "l"(c));
    return d;
}
__device__ __forceinline__ ull f32x2_dup(float x){
    ull d;
    asm("mov.b64 %0, {%1, %1};" : "=l"(d) : "f"(x));
    return d;
}
#define UNPACK2(lo, hi, v) asm("mov.b64 {%0, %1}, %2;" : "=f"(lo), "=f"(hi) : "l"(v))

// ---------------- persistent state (device globals; re-initialized every launch) ----
__device__ float g_h[NP*64];
__device__ float g_c[NP*64];
__device__ float g_ctx[NP*64];
__device__ float g_pos[NP*2];
__device__ float g_cur[NP*2];
__device__ float g_A[NP*64];     // A'[j] = h_j@W1_hj - cur_j . M   (spatial term folded)
__device__ float g_B[NP*64];     // B'[i] = h_i@W1_hi + bc + cur_i . M
__device__ float g_M[2*64];
__device__ float g_bc[64];
__device__ float g_xc[NP*128];   // precomputed b_in + [c,z] @ W_in[2:98]
__device__ float g_WihT[128*256];// W_ih transposed: [v][u]
__device__ float g_WhhT[64*256]; // W_hh transposed: [v][u]
__device__ int   g_cnt[TT*NP];          // valid-neighbor count per (t,i)
__device__ int   g_jidx[TT*NP*NP];      // compacted neighbor indices per (t,i)

__device__ __forceinline__ float sigmf(float x){ return 1.0f/(1.0f + expf(-x)); }

// ---------------- mask compaction for ALL steps, once -------------------------------
// grid = TT*NP blocks, 128 threads. nei is input-only; max is commutative so the
// (nondeterministic) compaction ORDER is irrelevant — the index SET is deterministic.
__global__ __launch_bounds__(128)
void k_mask(const int* __restrict__ nei)
{
    __shared__ int s_cnt;
    const int tid = threadIdx.x;
    const int row = blockIdx.x;            // row = t*NP + i
    if (tid == 0) s_cnt = 0;
    __syncthreads();
    const int* src = nei + (long)row*NP;
    int* dst = g_jidx + (long)row*NP;
    #pragma unroll
    for (int c=0;c<4;c++){
        int j = c*128 + tid;
        int v = src[j] > 0;
        unsigned bal = __ballot_sync(0xFFFFFFFFu, v);
        int lane = tid & 31;
        int base = 0;
        if (lane == 0) base = atomicAdd(&s_cnt, __popc(bal));
        base = __shfl_sync(0xFFFFFFFFu, base, 0);
        if (v) dst[base + __popc(bal & ((1u<<lane)-1u))] = j;
    }
    __syncthreads();
    if (tid == 0) g_cnt[row] = s_cnt;
}

// ---------------- init: copy state, fold W_sp/b_sp/b1 into M/bc, transpose LSTM W ---
__global__ void k_init(const float* __restrict__ last_pos, const float* __restrict__ obs,
                       const float* __restrict__ h0, const float* __restrict__ c0,
                       const float* __restrict__ W_sp, const float* __restrict__ b_sp,
                       const float* __restrict__ W1, const float* __restrict__ b1,
                       const float* __restrict__ W_ih, const float* __restrict__ W_hh)
{
    int idx = blockIdx.x*blockDim.x + threadIdx.x;
    if (idx < NP*64){ g_h[idx]=h0[idx]; g_c[idx]=c0[idx]; g_ctx[idx]=0.f; }
    if (idx < NP*2){ g_pos[idx]=last_pos[idx]; g_cur[idx]=obs[7*NP*2+idx]; }
    if (idx < 128){
        int f = idx>>6, m = idx&63; float s = 0.f;
        #pragma unroll 8
        for (int e=0;e<32;e++) s += W_sp[f*32+e]*W1[e*64+m];
        g_M[idx]=s;
    }
    if (idx < 64){
        float s = b1[idx];
        #pragma unroll 8
        for (int e=0;e<32;e++) s += b_sp[e]*W1[e*64+idx];
        g_bc[idx]=s;
    }
    // transposes (coalesced reads)
    if (idx < 256*128){
        int u = idx>>7, v = idx&127;
        g_WihT[v*256+u] = W_ih[idx];
    }
    if (idx < 256*64){
        int u = idx>>6, v = idx&63;
        g_WhhT[v*256+u] = W_hh[idx];
    }
}

// ---------------- x_const precompute: 128 blocks x 128 threads, 4 agents/block ------
__global__ __launch_bounds__(128)
void k_xc(const float* __restrict__ c_in, const float* __restrict__ z,
          const float* __restrict__ W_in, const float* __restrict__ b_in)
{
    __shared__ float sh[4][96];
    const int tid = threadIdx.x;
    const int abase = blockIdx.x*4;
    #pragma unroll
    for (int r=0;r<3;r++){
        int idx = r*128+tid; int a = idx/96, e = idx%96;
        sh[a][e] = (e < 64) ? c_in[(abase+a)*64 + e] : z[(abase+a)*32 + e-64];
    }
    __syncthreads();
    float s0=b_in[tid], s1=s0, s2=s0, s3=s0;
    #pragma unroll 8
    for (int e=0;e<96;e++){
        float w = W_in[(2+e)*128 + tid];
        s0 = fmaf(sh[0][e], w, s0);
        s1 = fmaf(sh[1][e], w, s1);
        s2 = fmaf(sh[2][e], w, s2);
        s3 = fmaf(sh[3][e], w, s3);
    }
    g_xc[(abase+0)*128+tid]=s0;
    g_xc[(abase+1)*128+tid]=s1;
    g_xc[(abase+2)*128+tid]=s2;
    g_xc[(abase+3)*128+tid]=s3;
}

// ---------------- per-agent kernel: post(t-1) + embed + LSTM(t) + A'/B'(t) ---------
// 4 agents per block, 256 threads, 128 blocks. t in [0,12]; t==12 does only post(11).
__global__ __launch_bounds__(256, 1)
void k_agent(int t,
             const float* __restrict__ eps,
             const float* __restrict__ W_in,
             const float* __restrict__ b_ih, const float* __restrict__ b_hh,
             const float* __restrict__ W_l2p, const float* __restrict__ b_l2p,
             const float* __restrict__ W1,
             float* __restrict__ out)
{
    __shared__ float sh_hold[4][64];
    __shared__ __align__(16) float sh_hT[64*4];    // h transposed [d][a]
    __shared__ float sh_ctx[4][64];
    __shared__ float sh_pos[4][2];
    __shared__ __align__(16) float sh_xT[128*4];   // x transposed [u][a]
    __shared__ float sh_hnew[4][64];
    __shared__ float buf[1024];

    const int tid = threadIdx.x;
    const int abase = blockIdx.x*4;

    // load previous h and ctx; build transposed h
    {
        int a = tid>>6, d = tid&63;
        int gi = (abase+a)*64+d;
        float hv = g_h[gi];
        sh_hold[a][d] = hv;
        sh_hT[d*4+a]  = hv;
        sh_ctx [a][d] = g_ctx[gi];
    }
    __syncthreads();

    if (t > 0){
        int tp = t-1;
        if (tid < 16){
            int a = tid>>2, o = tid&3;    // o: 0=mu0 1=mu1 2=lv0 3=lv1
            int f = o & 1; int lv = o>>1;
            const float* hh = &sh_hold[a][lv?32:0];
            float s = b_l2p[f];
            #pragma unroll 8
            for (int d=0; d<32; d++) s = fmaf(hh[d], W_l2p[d*2+f], s);
            #pragma unroll 8
            for (int k=0; k<64; k++) s = fmaf(sh_ctx[a][k], W_l2p[(32+k)*2+f], s);
            int i = abase+a;
            out[(lv?2:1)*(TT*NP*2) + tp*NP*2 + i*2 + f] = s;   // mean / var(logvar)
            buf[a*4+o] = s;
        }
        __syncthreads();
        if (tid < 8){
            int a = tid>>1, f = tid&1; int i = abase+a;
            float mu = buf[a*4+f], lvv = buf[a*4+2+f];
            float p = mu + eps[tp*NP*2 + i*2 + f]*expf(0.5f*lvv);
            out[tp*NP*2 + i*2 + f] = p;                        // pre_pos
            sh_pos[a][f] = p;
            g_pos[i*2+f] = p;
            g_cur[i*2+f] += p;
        }
        __syncthreads();
    } else {
        if (tid < 8){ int a = tid>>1, f = tid&1; sh_pos[a][f] = g_pos[(abase+a)*2+f]; }
        __syncthreads();
    }
    if (t == TT) return;

    // ---- x = relu(x_const + pos@W_in[0:2] + ctx@W_in[98:162]); store transposed ----
    {
        int u = tid & 127; int a0 = tid >> 7;       // agents a0, a0+2
        float s0 = g_xc[(abase+a0  )*128+u];
        float s1 = g_xc[(abase+a0+2)*128+u];
        float w0 = W_in[u], w1 = W_in[128+u];
        s0 = fmaf(sh_pos[a0  ][0], w0, fmaf(sh_pos[a0  ][1], w1, s0));
        s1 = fmaf(sh_pos[a0+2][0], w0, fmaf(sh_pos[a0+2][1], w1, s1));
        float w8[8];
        #pragma unroll
        for (int kb=0;kb<8;kb++){
            #pragma unroll
            for (int r=0;r<8;r++) w8[r] = W_in[(98+kb*8+r)*128+u];
            #pragma unroll
            for (int r=0;r<8;r++){
                s0 = fmaf(sh_ctx[a0  ][kb*8+r], w8[r], s0);
                s1 = fmaf(sh_ctx[a0+2][kb*8+r], w8[r], s1);
            }
        }
        sh_xT[u*4 + a0    ] = fmaxf(s0,0.f);
        sh_xT[u*4 + a0 + 2] = fmaxf(s1,0.f);
    }
    __syncthreads();

    // ---- gates = x@W_ih^T + h@W_hh^T + b ; transposed global weights, f32x2 --------
    // buf layout: agent-major, buf[a*256 + u] where u = gate*64 + dim
    {
        float binit = b_ih[tid] + b_hh[tid];
        ull acc01 = f32x2_dup(binit);
        ull acc23 = acc01;
        float w8[8];
        #pragma unroll
        for (int vb=0; vb<16; vb++){
            #pragma unroll
            for (int r=0;r<8;r++) w8[r] = g_WihT[(vb*8+r)*256+tid];
            #pragma unroll
            for (int r=0;r<8;r++){
                ulonglong2 xv = *(const ulonglong2*)(sh_xT + (vb*8+r)*4);
                ull wd = f32x2_dup(w8[r]);
                acc01 = f32x2_fma(xv.x, wd, acc01);
                acc23 = f32x2_fma(xv.y, wd, acc23);
            }
        }
        #pragma unroll
        for (int vb=0; vb<8; vb++){
            #pragma unroll
            for (int r=0;r<8;r++) w8[r] = g_WhhT[(vb*8+r)*256+tid];
            #pragma unroll
            for (int r=0;r<8;r++){
                ulonglong2 hv = *(const ulonglong2*)(sh_hT + (vb*8+r)*4);
                ull wd = f32x2_dup(w8[r]);
                acc01 = f32x2_fma(hv.x, wd, acc01);
                acc23 = f32x2_fma(hv.y, wd, acc23);
            }
        }
        float a0,a1,a2,a3;
        UNPACK2(a0,a1,acc01);
        UNPACK2(a2,a3,acc23);
        buf[0*256+tid]=a0; buf[1*256+tid]=a1; buf[2*256+tid]=a2; buf[3*256+tid]=a3;
    }
    __syncthreads();

    // ---- LSTM elementwise (256 threads = 4 agents x 64 dims) ----
    // buf is agent-major: buf[a*256 + gate*64 + d]
    {
        int a = tid>>6, d = tid&63; int i = abase+a;
        float ig = buf[a*256 +   0 + d];
        float fg = buf[a*256 +  64 + d];
        float gg = buf[a*256 + 128 + d];
        float og = buf[a*256 + 192 + d];
        float co = g_c[i*64+d];
        float cn = sigmf(fg)*co + sigmf(ig)*tanhf(gg);
        float hn = sigmf(og)*tanhf(cn);
        g_c[i*64+d] = cn;
        g_h[i*64+d] = hn;
        sh_hnew[a][d] = hn;
    }
    __syncthreads();

    // ---- A'[j]=h@W1[32:96] - cur_j.M,  B'[i]=h@W1[96:160]+bc + cur_i.M -------------
    {
        int m = tid & 63; int w = (tid>>6)&1; int ah = tid>>7;  // agents ah, ah+2
        float s0 = w ? g_bc[m] : 0.f; float s1 = s0;
        const float* Wp = W1 + (32 + w*64)*64 + m;
        float w8[8];
        #pragma unroll
        for (int db=0; db<8; db++){
            #pragma unroll
            for (int r=0;r<8;r++) w8[r] = Wp[(db*8+r)*64];
            #pragma unroll
            for (int r=0;r<8;r++){
                s0 = fmaf(sh_hnew[ah  ][db*8+r], w8[r], s0);
                s1 = fmaf(sh_hnew[ah+2][db*8+r], w8[r], s1);
            }
        }
        float m0 = g_M[m], m1 = g_M[64+m];
        float sg = w ? 1.f : -1.f;
        float cx0 = g_cur[(abase+ah  )*2], cy0 = g_cur[(abase+ah  )*2+1];
        float cx1 = g_cur[(abase+ah+2)*2], cy1 = g_cur[(abase+ah+2)*2+1];
        s0 = fmaf(sg*cx0, m0, fmaf(sg*cy0, m1, s0));
        s1 = fmaf(sg*cx1, m0, fmaf(sg*cy1, m1, s1));
        float* dst = w ? g_B : g_A;
        dst[(abase+ah  )*64+m] = s0;
        dst[(abase+ah+2)*64+m] = s1;
    }
}

// ---------------- pooling kernel: 512 blocks (1 row i), 256 threads, 128-pair tiles -
// Round-8 proven config (256,3 / regs~80). Mask compaction is PRECOMPUTED by k_mask:
// block reads g_cnt + g_jidx (L1-hot broadcast LDG) and goes straight to the GEMM.
__global__ __launch_bounds__(256, 3)
void k_pool(int t, const float* __restrict__ W2, const float* __restrict__ b2)
{
    __shared__ __align__(16) float sh_h1[64*132];  // [m][p] stride 132; red aliased

    const int tid = threadIdx.x;
    const int i = blockIdx.x;
    const float4* W2v = (const float4*)W2;         // [m][kq] quads

    const int row = t*NP + i;
    const int cnt = g_cnt[row];
    const int* __restrict__ jrow = g_jidx + (long)row*NP;
    const int ntiles = (cnt + 127) >> 7;

    const int mm = tid & 63, q = tid >> 6;      // stage-1 mapping
    const float Bi = g_B[i*64+mm];

    const int kq = tid & 15, jg = tid >> 4;     // 16 j-groups of 8, 16 k-quads
    float b2r[4];
    #pragma unroll
    for (int kk=0;kk<4;kk++) b2r[kk] = b2[kq*4+kk];
    float cacc[4] = {0.f,0.f,0.f,0.f};

    for (int jt=0; jt<ntiles; jt++){
        const int tile_cnt = min(128, cnt - jt*128);
        __syncthreads();                         // protect sh_h1 reuse

        // stage 1: h1 for valid pairs x 64 m; batched j then A loads; skip empty chunks
        #pragma unroll
        for (int rb=0; rb<4; rb++){
            if (rb*32 < tile_cnt){
                int j8[8];
                #pragma unroll
                for (int r2=0; r2<8; r2++){
                    int gp = jt*128 + (rb*8+r2)*4 + q;
                    j8[r2] = jrow[(gp < cnt) ? gp : 0];
                }
                float a8[8];
                #pragma unroll
                for (int r2=0; r2<8; r2++)
                    a8[r2] = g_A[j8[r2]*64 + mm];
                #pragma unroll
                for (int r2=0; r2<8; r2++){
                    int p = (rb*8+r2)*4 + q;
                    sh_h1[mm*132 + p] = fmaxf(a8[r2] + Bi, 0.f);
                }
            }
        }
        __syncthreads();

        // stage 2: packed f32x2 GEMM, 4 j-pairs x 4 k per thread; skip idle warps
        if (jg*8 < tile_cnt){
            ull acc2[4][4];
            #pragma unroll
            for (int jp=0;jp<4;jp++)
                #pragma unroll
                for (int kk=0;kk<4;kk++) acc2[jp][kk] = 0ull;

            #pragma unroll 8
            for (int m=0;m<64;m++){
                const float4 wv = __ldg(W2v + m*16 + kq);
                ull w0 = f32x2_dup(wv.x), w1 = f32x2_dup(wv.y);
                ull w2 = f32x2_dup(wv.z), w3 = f32x2_dup(wv.w);
                const ull* hp = (const ull*)(sh_h1 + m*132 + (jg<<3));
                ulonglong2 hA = *(const ulonglong2*)(hp);
                ulonglong2 hB = *(const ulonglong2*)(hp+2);
                acc2[0][0]=f32x2_fma(hA.x,w0,acc2[0][0]);
                acc2[0][1]=f32x2_fma(hA.x,w1,acc2[0][1]);
                acc2[0][2]=f32x2_fma(hA.x,w2,acc2[0][2]);
                acc2[0][3]=f32x2_fma(hA.x,w3,acc2[0][3]);
                acc2[1][0]=f32x2_fma(hA.y,w0,acc2[1][0]);
                acc2[1][1]=f32x2_fma(hA.y,w1,acc2[1][1]);
                acc2[1][2]=f32x2_fma(hA.y,w2,acc2[1][2]);
                acc2[1][3]=f32x2_fma(hA.y,w3,acc2[1][3]);
                acc2[2][0]=f32x2_fma(hB.x,w0,acc2[2][0]);
                acc2[2][1]=f32x2_fma(hB.x,w1,acc2[2][1]);
                acc2[2][2]=f32x2_fma(hB.x,w2,acc2[2][2]);
                acc2[2][3]=f32x2_fma(hB.x,w3,acc2[2][3]);
                acc2[3][0]=f32x2_fma(hB.y,w0,acc2[3][0]);
                acc2[3][1]=f32x2_fma(hB.y,w1,acc2[3][1]);
                acc2[3][2]=f32x2_fma(hB.y,w2,acc2[3][2]);
                acc2[3][3]=f32x2_fma(hB.y,w3,acc2[3][3]);
            }

            #pragma unroll
            for (int jp=0;jp<4;jp++){
                int gp0 = jt*128 + jg*8 + jp*2;
                #pragma unroll
                for (int kk=0;kk<4;kk++){
                    float lo, hi;
                    UNPACK2(lo, hi, acc2[jp][kk]);
                    if (gp0     < cnt) cacc[kk] = fmaxf(cacc[kk], lo + b2r[kk]);
                    if (gp0 + 1 < cnt) cacc[kk] = fmaxf(cacc[kk], hi + b2r[kk]);
                }
            }
        }
    }

    // final reduction over 16 jg groups; alias reduction buffer onto sh_h1
    __syncthreads();
    float* sh_red = sh_h1;
    #pragma unroll
    for (int kk=0;kk<4;kk++) sh_red[jg*64 + kq*4+kk] = cacc[kk];
    __syncthreads();
    if (tid < 64){
        float v = sh_red[tid];
        #pragma unroll
        for (int g=1; g<16; g++) v = fmaxf(v, sh_red[g*64 + tid]);
        g_ctx[i*64 + tid] = v;
    }
}

// ---------------- launch ------------------------------------------------------------
extern "C" void kernel_launch(void* const* d_in, const int* in_sizes, int n_in,
                              void* d_out, int out_size)
{
    const float* last_pos = (const float*)d_in[0];
    const float* c_in     = (const float*)d_in[1];
    const float* z        = (const float*)d_in[2];
    const float* obs      = (const float*)d_in[3];
    const int*   nei      = (const int*)  d_in[4];
    // d_in[5] nei_num_index: unused by reference
    const float* h0       = (const float*)d_in[6];
    const float* c0       = (const float*)d_in[7];
    const float* eps      = (const float*)d_in[8];
    const float* W_in     = (const float*)d_in[9];
    const float* b_in     = (const float*)d_in[10];
    const float* W_ih     = (const float*)d_in[11];
    const float* W_hh     = (const float*)d_in[12];
    const float* b_ih     = (const float*)d_in[13];
    const float* b_hh     = (const float*)d_in[14];
    const float* W_l2p    = (const float*)d_in[15];
    const float* b_l2p    = (const float*)d_in[16];
    const float* W_sp     = (const float*)d_in[17];
    const float* b_sp     = (const float*)d_in[18];
    const float* W1       = (const float*)d_in[19];
    const float* b1       = (const float*)d_in[20];
    const float* W2       = (const float*)d_in[21];
    const float* b2       = (const float*)d_in[22];
    float* out = (float*)d_out;

    k_init<<<128, 256>>>(last_pos, obs, h0, c0, W_sp, b_sp, W1, b1, W_ih, W_hh);
    k_mask<<<TT*NP, 128>>>(nei);
    k_xc<<<128, 128>>>(c_in, z, W_in, b_in);

    for (int t=0; t<TT; t++){
        k_agent<<<128, 256>>>(t, eps, W_in, b_ih, b_hh, W_l2p, b_l2p, W1, out);
        k_pool<<<512, 256>>>(t, W2, b2);
    }
    // final post (outputs for t = 11)
    k_agent<<<128, 256>>>(TT, eps, W_in, b_ih, b_hh, W_l2p, b_l2p, W1, out);
}

// round 13
// speedup vs baseline: 1.0295x; 1.0295x over previous
#include <cuda_runtime.h>
#include <math.h>
#include <cstdint>

#define NP 512
#define TT 12

typedef unsigned long long ull;

// ---------------- f32x2 packed helpers (sm_103a) ------------------------------------
__device__ __forceinline__ ull f32x2_fma(ull a, ull b, ull c){
    ull d;
    asm("fma.rn.f32x2 %0, %1, %2, %3;" : "=l"(d) : "l"(a), "l"(b), "l"(c));
    return d;
}
__device__ __forceinline__ ull f32x2_dup(float x){
    ull d;
    asm("mov.b64 %0, {%1, %1};" : "=l"(d) : "f"(x));
    return d;
}
#define UNPACK2(lo, hi, v) asm("mov.b64 {%0, %1}, %2;" : "=f"(lo), "=f"(hi) : "l"(v))

// ---------------- persistent state (device globals; re-initialized every launch) ----
__device__ float g_h[NP*64];
__device__ float g_c[NP*64];
__device__ float g_ctx[NP*64];
__device__ float g_pos[NP*2];
__device__ float g_cur[NP*2];
__device__ float g_A[NP*64];     // A'[j] = h_j@W1_hj - cur_j . M   (spatial term folded)
__device__ float g_B[NP*64];     // B'[i] = h_i@W1_hi + bc + cur_i . M
__device__ float g_M[2*64];
__device__ float g_bc[64];
__device__ float g_xc[NP*128];   // precomputed b_in + [c,z] @ W_in[2:98]
__device__ float g_WihT[128*256];// W_ih transposed: [v][u]
__device__ float g_WhhT[64*256]; // W_hh transposed: [v][u]

__device__ __forceinline__ float sigmf(float x){ return 1.0f/(1.0f + expf(-x)); }

// ---------------- init: copy state, fold W_sp/b_sp/b1 into M/bc, transpose LSTM W ---
__global__ void k_init(const float* __restrict__ last_pos, const float* __restrict__ obs,
                       const float* __restrict__ h0, const float* __restrict__ c0,
                       const float* __restrict__ W_sp, const float* __restrict__ b_sp,
                       const float* __restrict__ W1, const float* __restrict__ b1,
                       const float* __restrict__ W_ih, const float* __restrict__ W_hh)
{
    int idx = blockIdx.x*blockDim.x + threadIdx.x;
    if (idx < NP*64){ g_h[idx]=h0[idx]; g_c[idx]=c0[idx]; g_ctx[idx]=0.f; }
    if (idx < NP*2){ g_pos[idx]=last_pos[idx]; g_cur[idx]=obs[7*NP*2+idx]; }
    if (idx < 128){
        int f = idx>>6, m = idx&63; float s = 0.f;
        #pragma unroll 8
        for (int e=0;e<32;e++) s += W_sp[f*32+e]*W1[e*64+m];
        g_M[idx]=s;
    }
    if (idx < 64){
        float s = b1[idx];
        #pragma unroll 8
        for (int e=0;e<32;e++) s += b_sp[e]*W1[e*64+idx];
        g_bc[idx]=s;
    }
    // transposes (coalesced reads)
    if (idx < 256*128){
        int u = idx>>7, v = idx&127;
        g_WihT[v*256+u] = W_ih[idx];
    }
    if (idx < 256*64){
        int u = idx>>6, v = idx&63;
        g_WhhT[v*256+u] = W_hh[idx];
    }
}

// ---------------- x_const precompute: 128 blocks x 128 threads, 4 agents/block ------
__global__ __launch_bounds__(128)
void k_xc(const float* __restrict__ c_in, const float* __restrict__ z,
          const float* __restrict__ W_in, const float* __restrict__ b_in)
{
    __shared__ float sh[4][96];
    const int tid = threadIdx.x;
    const int abase = blockIdx.x*4;
    #pragma unroll
    for (int r=0;r<3;r++){
        int idx = r*128+tid; int a = idx/96, e = idx%96;
        sh[a][e] = (e < 64) ? c_in[(abase+a)*64 + e] : z[(abase+a)*32 + e-64];
    }
    __syncthreads();
    float s0=b_in[tid], s1=s0, s2=s0, s3=s0;
    #pragma unroll 8
    for (int e=0;e<96;e++){
        float w = W_in[(2+e)*128 + tid];
        s0 = fmaf(sh[0][e], w, s0);
        s1 = fmaf(sh[1][e], w, s1);
        s2 = fmaf(sh[2][e], w, s2);
        s3 = fmaf(sh[3][e], w, s3);
    }
    g_xc[(abase+0)*128+tid]=s0;
    g_xc[(abase+1)*128+tid]=s1;
    g_xc[(abase+2)*128+tid]=s2;
    g_xc[(abase+3)*128+tid]=s3;
}

// ---------------- per-agent kernel: post(t-1) + embed + LSTM(t) + A'/B'(t) ---------
// 4 agents per block, 256 threads, 128 blocks. t in [0,12]; t==12 does only post(11).
__global__ __launch_bounds__(256, 1)
void k_agent(int t,
             const float* __restrict__ eps,
             const float* __restrict__ W_in,
             const float* __restrict__ b_ih, const float* __restrict__ b_hh,
             const float* __restrict__ W_l2p, const float* __restrict__ b_l2p,
             const float* __restrict__ W1,
             float* __restrict__ out)
{
    __shared__ float sh_hold[4][64];
    __shared__ __align__(16) float sh_hT[64*4];    // h transposed [d][a]
    __shared__ float sh_ctx[4][64];
    __shared__ float sh_pos[4][2];
    __shared__ __align__(16) float sh_xT[128*4];   // x transposed [u][a]
    __shared__ float sh_hnew[4][64];
    __shared__ float buf[1024];

    const int tid = threadIdx.x;
    const int abase = blockIdx.x*4;

    // load previous h and ctx; build transposed h
    {
        int a = tid>>6, d = tid&63;
        int gi = (abase+a)*64+d;
        float hv = g_h[gi];
        sh_hold[a][d] = hv;
        sh_hT[d*4+a]  = hv;
        sh_ctx [a][d] = g_ctx[gi];
    }
    __syncthreads();

    if (t > 0){
        int tp = t-1;
        if (tid < 16){
            int a = tid>>2, o = tid&3;    // o: 0=mu0 1=mu1 2=lv0 3=lv1
            int f = o & 1; int lv = o>>1;
            const float* hh = &sh_hold[a][lv?32:0];
            float s = b_l2p[f];
            #pragma unroll 8
            for (int d=0; d<32; d++) s = fmaf(hh[d], W_l2p[d*2+f], s);
            #pragma unroll 8
            for (int k=0; k<64; k++) s = fmaf(sh_ctx[a][k], W_l2p[(32+k)*2+f], s);
            int i = abase+a;
            out[(lv?2:1)*(TT*NP*2) + tp*NP*2 + i*2 + f] = s;   // mean / var(logvar)
            buf[a*4+o] = s;
        }
        __syncthreads();
        if (tid < 8){
            int a = tid>>1, f = tid&1; int i = abase+a;
            float mu = buf[a*4+f], lvv = buf[a*4+2+f];
            float p = mu + eps[tp*NP*2 + i*2 + f]*expf(0.5f*lvv);
            out[tp*NP*2 + i*2 + f] = p;                        // pre_pos
            sh_pos[a][f] = p;
            g_pos[i*2+f] = p;
            g_cur[i*2+f] += p;
        }
        __syncthreads();
    } else {
        if (tid < 8){ int a = tid>>1, f = tid&1; sh_pos[a][f] = g_pos[(abase+a)*2+f]; }
        __syncthreads();
    }
    if (t == TT) return;

    // ---- x = relu(x_const + pos@W_in[0:2] + ctx@W_in[98:162]); store transposed ----
    {
        int u = tid & 127; int a0 = tid >> 7;       // agents a0, a0+2
        float s0 = g_xc[(abase+a0  )*128+u];
        float s1 = g_xc[(abase+a0+2)*128+u];
        float w0 = W_in[u], w1 = W_in[128+u];
        s0 = fmaf(sh_pos[a0  ][0], w0, fmaf(sh_pos[a0  ][1], w1, s0));
        s1 = fmaf(sh_pos[a0+2][0], w0, fmaf(sh_pos[a0+2][1], w1, s1));
        float w8[8];
        #pragma unroll
        for (int kb=0;kb<8;kb++){
            #pragma unroll
            for (int r=0;r<8;r++) w8[r] = W_in[(98+kb*8+r)*128+u];
            #pragma unroll
            for (int r=0;r<8;r++){
                s0 = fmaf(sh_ctx[a0  ][kb*8+r], w8[r], s0);
                s1 = fmaf(sh_ctx[a0+2][kb*8+r], w8[r], s1);
            }
        }
        sh_xT[u*4 + a0    ] = fmaxf(s0,0.f);
        sh_xT[u*4 + a0 + 2] = fmaxf(s1,0.f);
    }
    __syncthreads();

    // ---- gates = x@W_ih^T + h@W_hh^T + b ; transposed global weights, f32x2 --------
    // buf layout: agent-major, buf[a*256 + u] where u = gate*64 + dim
    {
        float binit = b_ih[tid] + b_hh[tid];
        ull acc01 = f32x2_dup(binit);
        ull acc23 = acc01;
        float w8[8];
        #pragma unroll
        for (int vb=0; vb<16; vb++){
            #pragma unroll
            for (int r=0;r<8;r++) w8[r] = g_WihT[(vb*8+r)*256+tid];
            #pragma unroll
            for (int r=0;r<8;r++){
                ulonglong2 xv = *(const ulonglong2*)(sh_xT + (vb*8+r)*4);
                ull wd = f32x2_dup(w8[r]);
                acc01 = f32x2_fma(xv.x, wd, acc01);
                acc23 = f32x2_fma(xv.y, wd, acc23);
            }
        }
        #pragma unroll
        for (int vb=0; vb<8; vb++){
            #pragma unroll
            for (int r=0;r<8;r++) w8[r] = g_WhhT[(vb*8+r)*256+tid];
            #pragma unroll
            for (int r=0;r<8;r++){
                ulonglong2 hv = *(const ulonglong2*)(sh_hT + (vb*8+r)*4);
                ull wd = f32x2_dup(w8[r]);
                acc01 = f32x2_fma(hv.x, wd, acc01);
                acc23 = f32x2_fma(hv.y, wd, acc23);
            }
        }
        float a0,a1,a2,a3;
        UNPACK2(a0,a1,acc01);
        UNPACK2(a2,a3,acc23);
        buf[0*256+tid]=a0; buf[1*256+tid]=a1; buf[2*256+tid]=a2; buf[3*256+tid]=a3;
    }
    __syncthreads();

    // ---- LSTM elementwise (256 threads = 4 agents x 64 dims) ----
    // buf is agent-major: buf[a*256 + gate*64 + d]
    {
        int a = tid>>6, d = tid&63; int i = abase+a;
        float ig = buf[a*256 +   0 + d];
        float fg = buf[a*256 +  64 + d];
        float gg = buf[a*256 + 128 + d];
        float og = buf[a*256 + 192 + d];
        float co = g_c[i*64+d];
        float cn = sigmf(fg)*co + sigmf(ig)*tanhf(gg);
        float hn = sigmf(og)*tanhf(cn);
        g_c[i*64+d] = cn;
        g_h[i*64+d] = hn;
        sh_hnew[a][d] = hn;
    }
    __syncthreads();

    // ---- A'[j]=h@W1[32:96] - cur_j.M,  B'[i]=h@W1[96:160]+bc + cur_i.M -------------
    {
        int m = tid & 63; int w = (tid>>6)&1; int ah = tid>>7;  // agents ah, ah+2
        float s0 = w ? g_bc[m] : 0.f; float s1 = s0;
        const float* Wp = W1 + (32 + w*64)*64 + m;
        float w8[8];
        #pragma unroll
        for (int db=0; db<8; db++){
            #pragma unroll
            for (int r=0;r<8;r++) w8[r] = Wp[(db*8+r)*64];
            #pragma unroll
            for (int r=0;r<8;r++){
                s0 = fmaf(sh_hnew[ah  ][db*8+r], w8[r], s0);
                s1 = fmaf(sh_hnew[ah+2][db*8+r], w8[r], s1);
            }
        }
        float m0 = g_M[m], m1 = g_M[64+m];
        float sg = w ? 1.f : -1.f;
        float cx0 = g_cur[(abase+ah  )*2], cy0 = g_cur[(abase+ah  )*2+1];
        float cx1 = g_cur[(abase+ah+2)*2], cy1 = g_cur[(abase+ah+2)*2+1];
        s0 = fmaf(sg*cx0, m0, fmaf(sg*cy0, m1, s0));
        s1 = fmaf(sg*cx1, m0, fmaf(sg*cy1, m1, s1));
        float* dst = w ? g_B : g_A;
        dst[(abase+ah  )*64+m] = s0;
        dst[(abase+ah+2)*64+m] = s1;
    }
}

// ---------------- pooling kernel: 512 blocks (1 row i), 256 threads, 128-pair tiles -
// Round-8 proven structure. h1 stride 130 (bank delta 2 -> 2-way STS conflict instead
// of 4-way at stride 132); stage-2 h1 reads are broadcasts, done as 4x LDS.64.
__global__ __launch_bounds__(256, 3)
void k_pool(int t, const int* __restrict__ nei,
            const float* __restrict__ W2, const float* __restrict__ b2)
{
    __shared__ __align__(16) float sh_h1[64*130];  // [m][p] stride 130; red aliased
    __shared__ int   sh_jidx[NP];
    __shared__ int   sh_cnt;

    const int tid = threadIdx.x;
    const int i = blockIdx.x;
    const float4* W2v = (const float4*)W2;         // [m][kq] quads

    if (tid == 0) sh_cnt = 0;
    __syncthreads();

    // ---- compact valid neighbor indices (max is commutative; order irrelevant) ----
    {
        const int* row = nei + (long)t*NP*NP + (long)i*NP;
        #pragma unroll
        for (int c=0;c<2;c++){
            int j = c*256 + tid;
            int v = row[j] > 0;
            unsigned bal = __ballot_sync(0xFFFFFFFFu, v);
            int lane = tid & 31;
            int base = 0;
            if (lane == 0) base = atomicAdd(&sh_cnt, __popc(bal));
            base = __shfl_sync(0xFFFFFFFFu, base, 0);
            if (v) sh_jidx[base + __popc(bal & ((1u<<lane)-1u))] = j;
        }
    }
    __syncthreads();
    const int cnt = sh_cnt;
    const int ntiles = (cnt + 127) >> 7;

    const int mm = tid & 63, q = tid >> 6;      // stage-1 mapping
    const float Bi = g_B[i*64+mm];

    const int kq = tid & 15, jg = tid >> 4;     // 16 j-groups of 8, 16 k-quads
    float b2r[4];
    #pragma unroll
    for (int kk=0;kk<4;kk++) b2r[kk] = b2[kq*4+kk];
    float cacc[4] = {0.f,0.f,0.f,0.f};

    for (int jt=0; jt<ntiles; jt++){
        const int tile_cnt = min(128, cnt - jt*128);
        __syncthreads();                         // protect sh_h1 reuse

        // stage 1: h1 for valid pairs x 64 m; batched loads, skip invalid 32-chunks
        #pragma unroll
        for (int rb=0; rb<4; rb++){
            if (rb*32 < tile_cnt){
                float a8[8];
                #pragma unroll
                for (int r2=0; r2<8; r2++){
                    int p = (rb*8+r2)*4 + q;
                    int gp = jt*128 + p;
                    int j = sh_jidx[(gp < cnt) ? gp : 0];
                    a8[r2] = g_A[j*64 + mm];
                }
                #pragma unroll
                for (int r2=0; r2<8; r2++){
                    int p = (rb*8+r2)*4 + q;
                    sh_h1[mm*130 + p] = fmaxf(a8[r2] + Bi, 0.f);
                }
            }
        }
        __syncthreads();

        // stage 2: packed f32x2 GEMM, 4 j-pairs x 4 k per thread; skip idle warps
        if (jg*8 < tile_cnt){
            ull acc2[4][4];
            #pragma unroll
            for (int jp=0;jp<4;jp++)
                #pragma unroll
                for (int kk=0;kk<4;kk++) acc2[jp][kk] = 0ull;

            #pragma unroll 8
            for (int m=0;m<64;m++){
                const float4 wv = __ldg(W2v + m*16 + kq);
                ull w0 = f32x2_dup(wv.x), w1 = f32x2_dup(wv.y);
                ull w2 = f32x2_dup(wv.z), w3 = f32x2_dup(wv.w);
                const ull* hp = (const ull*)(sh_h1 + m*130 + (jg<<3));
                ull h0 = hp[0], h1 = hp[1], h2 = hp[2], h3 = hp[3];
                acc2[0][0]=f32x2_fma(h0,w0,acc2[0][0]);
                acc2[0][1]=f32x2_fma(h0,w1,acc2[0][1]);
                acc2[0][2]=f32x2_fma(h0,w2,acc2[0][2]);
                acc2[0][3]=f32x2_fma(h0,w3,acc2[0][3]);
                acc2[1][0]=f32x2_fma(h1,w0,acc2[1][0]);
                acc2[1][1]=f32x2_fma(h1,w1,acc2[1][1]);
                acc2[1][2]=f32x2_fma(h1,w2,acc2[1][2]);
                acc2[1][3]=f32x2_fma(h1,w3,acc2[1][3]);
                acc2[2][0]=f32x2_fma(h2,w0,acc2[2][0]);
                acc2[2][1]=f32x2_fma(h2,w1,acc2[2][1]);
                acc2[2][2]=f32x2_fma(h2,w2,acc2[2][2]);
                acc2[2][3]=f32x2_fma(h2,w3,acc2[2][3]);
                acc2[3][0]=f32x2_fma(h3,w0,acc2[3][0]);
                acc2[3][1]=f32x2_fma(h3,w1,acc2[3][1]);
                acc2[3][2]=f32x2_fma(h3,w2,acc2[3][2]);
                acc2[3][3]=f32x2_fma(h3,w3,acc2[3][3]);
            }

            #pragma unroll
            for (int jp=0;jp<4;jp++){
                int gp0 = jt*128 + jg*8 + jp*2;
                #pragma unroll
                for (int kk=0;kk<4;kk++){
                    float lo, hi;
                    UNPACK2(lo, hi, acc2[jp][kk]);
                    if (gp0     < cnt) cacc[kk] = fmaxf(cacc[kk], lo + b2r[kk]);
                    if (gp0 + 1 < cnt) cacc[kk] = fmaxf(cacc[kk], hi + b2r[kk]);
                }
            }
        }
    }

    // final reduction over 16 jg groups; alias reduction buffer onto sh_h1
    __syncthreads();
    float* sh_red = sh_h1;
    #pragma unroll
    for (int kk=0;kk<4;kk++) sh_red[jg*64 + kq*4+kk] = cacc[kk];
    __syncthreads();
    if (tid < 64){
        float v = sh_red[tid];
        #pragma unroll
        for (int g=1; g<16; g++) v = fmaxf(v, sh_red[g*64 + tid]);
        g_ctx[i*64 + tid] = v;
    }
}

// ---------------- launch ------------------------------------------------------------
extern "C" void kernel_launch(void* const* d_in, const int* in_sizes, int n_in,
                              void* d_out, int out_size)
{
    const float* last_pos = (const float*)d_in[0];
    const float* c_in     = (const float*)d_in[1];
    const float* z        = (const float*)d_in[2];
    const float* obs      = (const float*)d_in[3];
    const int*   nei      = (const int*)  d_in[4];
    // d_in[5] nei_num_index: unused by reference
    const float* h0       = (const float*)d_in[6];
    const float* c0       = (const float*)d_in[7];
    const float* eps      = (const float*)d_in[8];
    const float* W_in     = (const float*)d_in[9];
    const float* b_in     = (const float*)d_in[10];
    const float* W_ih     = (const float*)d_in[11];
    const float* W_hh     = (const float*)d_in[12];
    const float* b_ih     = (const float*)d_in[13];
    const float* b_hh     = (const float*)d_in[14];
    const float* W_l2p    = (const float*)d_in[15];
    const float* b_l2p    = (const float*)d_in[16];
    const float* W_sp     = (const float*)d_in[17];
    const float* b_sp     = (const float*)d_in[18];
    const float* W1       = (const float*)d_in[19];
    const float* b1       = (const float*)d_in[20];
    const float* W2       = (const float*)d_in[21];
    const float* b2       = (const float*)d_in[22];
    float* out = (float*)d_out;

    k_init<<<128, 256>>>(last_pos, obs, h0, c0, W_sp, b_sp, W1, b1, W_ih, W_hh);
    k_xc<<<128, 128>>>(c_in, z, W_in, b_in);

    for (int t=0; t<TT; t++){
        k_agent<<<128, 256>>>(t, eps, W_in, b_ih, b_hh, W_l2p, b_l2p, W1, out);
        k_pool<<<512, 256>>>(t, nei, W2, b2);
    }
    // final post (outputs for t = 11)
    k_agent<<<128, 256>>>(TT, eps, W_in, b_ih, b_hh, W_l2p, b_l2p, W1, out);
}

// round 15
// speedup vs baseline: 1.3709x; 1.3316x over previous
#include <cuda_runtime.h>
#include <cuda_bf16.h>
#include <math.h>
#include <cstdint>

#define NP 512
#define TT 12

typedef unsigned long long ull;

// ---------------- f32x2 packed helpers (sm_103a) ------------------------------------
__device__ __forceinline__ ull f32x2_fma(ull a, ull b, ull c){
    ull d;
    asm("fma.rn.f32x2 %0, %1, %2, %3;" : "=l"(d) : "l"(a), "l"(b), "l"(c));
    return d;
}
__device__ __forceinline__ ull f32x2_dup(float x){
    ull d;
    asm("mov.b64 %0, {%1, %1};" : "=l"(d) : "f"(x));
    return d;
}
#define UNPACK2(lo, hi, v) asm("mov.b64 {%0, %1}, %2;" : "=f"(lo), "=f"(hi) : "l"(v))

// ---------------- warp-level tensor core helpers (sm_80+ PTX, compiles at compute_103)
__device__ __forceinline__ uint32_t smem_to_u32(const void* p) {
    uint32_t a;
    asm("{ .reg .u64 t; cvta.to.shared.u64 t, %1; cvt.u32.u64 %0, t; }" : "=r"(a) : "l"(p));
    return a;
}
__device__ __forceinline__ void ldsm_x4(uint32_t* r, uint32_t addr){
    asm volatile("ldmatrix.sync.aligned.m8n8.x4.shared.b16 {%0,%1,%2,%3}, [%4];"
        : "=r"(r[0]), "=r"(r[1]), "=r"(r[2]), "=r"(r[3]) : "r"(addr));
}
__device__ __forceinline__ void ldsm_x2t(uint32_t* r, uint32_t addr){
    asm volatile("ldmatrix.sync.aligned.m8n8.x2.trans.shared.b16 {%0,%1}, [%2];"
        : "=r"(r[0]), "=r"(r[1]) : "r"(addr));
}
__device__ __forceinline__ void mma16816(float* d, const uint32_t* a, const uint32_t* b){
    asm volatile("mma.sync.aligned.m16n8k16.row.col.f32.bf16.bf16.f32 "
        "{%0,%1,%2,%3}, {%4,%5,%6,%7}, {%8,%9}, {%0,%1,%2,%3};"
        : "+f"(d[0]), "+f"(d[1]), "+f"(d[2]), "+f"(d[3])
        : "r"(a[0]), "r"(a[1]), "r"(a[2]), "r"(a[3]), "r"(b[0]), "r"(b[1]));
}

// ---------------- persistent state (device globals; re-initialized every launch) ----
__device__ float g_h[NP*64];
__device__ float g_c[NP*64];
__device__ float g_ctx[NP*64];
__device__ float g_pos[NP*2];
__device__ float g_cur[NP*2];
__device__ float g_A[NP*64];     // A'[j] = h_j@W1_hj - cur_j . M   (spatial term folded)
__device__ float g_B[NP*64];     // B'[i] = h_i@W1_hi + bc + cur_i . M
__device__ float g_M[2*64];
__device__ float g_bc[64];
__device__ float g_xc[NP*128];   // precomputed b_in + [c,z] @ W_in[2:98]
__device__ float g_WihT[128*256];// W_ih transposed: [v][u]
__device__ float g_WhhT[64*256]; // W_hh transposed: [v][u]
__device__ __nv_bfloat16 g_W2hi[64*64];  // W2 [m][k] bf16 split (K x N row-major for mma)
__device__ __nv_bfloat16 g_W2lo[64*64];

__device__ __forceinline__ float sigmf(float x){ return 1.0f/(1.0f + expf(-x)); }

// ---------------- init: copy state, fold weights, transposes, W2 bf16 split ---------
__global__ void k_init(const float* __restrict__ last_pos, const float* __restrict__ obs,
                       const float* __restrict__ h0, const float* __restrict__ c0,
                       const float* __restrict__ W_sp, const float* __restrict__ b_sp,
                       const float* __restrict__ W1, const float* __restrict__ b1,
                       const float* __restrict__ W_ih, const float* __restrict__ W_hh,
                       const float* __restrict__ W2)
{
    int idx = blockIdx.x*blockDim.x + threadIdx.x;
    if (idx < NP*64){ g_h[idx]=h0[idx]; g_c[idx]=c0[idx]; g_ctx[idx]=0.f; }
    if (idx < NP*2){ g_pos[idx]=last_pos[idx]; g_cur[idx]=obs[7*NP*2+idx]; }
    if (idx < 128){
        int f = idx>>6, m = idx&63; float s = 0.f;
        #pragma unroll 8
        for (int e=0;e<32;e++) s += W_sp[f*32+e]*W1[e*64+m];
        g_M[idx]=s;
    }
    if (idx < 64){
        float s = b1[idx];
        #pragma unroll 8
        for (int e=0;e<32;e++) s += b_sp[e]*W1[e*64+idx];
        g_bc[idx]=s;
    }
    if (idx < 256*128){
        int u = idx>>7, v = idx&127;
        g_WihT[v*256+u] = W_ih[idx];
    }
    if (idx < 256*64){
        int u = idx>>6, v = idx&63;
        g_WhhT[v*256+u] = W_hh[idx];
    }
    if (idx < 64*64){
        float w = W2[idx];                       // [m][k] row-major, as mma B needs
        __nv_bfloat16 hi = __float2bfloat16(w);
        g_W2hi[idx] = hi;
        g_W2lo[idx] = __float2bfloat16(w - __bfloat162float(hi));
    }
}

// ---------------- x_const precompute: 128 blocks x 128 threads, 4 agents/block ------
__global__ __launch_bounds__(128)
void k_xc(const float* __restrict__ c_in, const float* __restrict__ z,
          const float* __restrict__ W_in, const float* __restrict__ b_in)
{
    __shared__ float sh[4][96];
    const int tid = threadIdx.x;
    const int abase = blockIdx.x*4;
    #pragma unroll
    for (int r=0;r<3;r++){
        int idx = r*128+tid; int a = idx/96, e = idx%96;
        sh[a][e] = (e < 64) ? c_in[(abase+a)*64 + e] : z[(abase+a)*32 + e-64];
    }
    __syncthreads();
    float s0=b_in[tid], s1=s0, s2=s0, s3=s0;
    #pragma unroll 8
    for (int e=0;e<96;e++){
        float w = W_in[(2+e)*128 + tid];
        s0 = fmaf(sh[0][e], w, s0);
        s1 = fmaf(sh[1][e], w, s1);
        s2 = fmaf(sh[2][e], w, s2);
        s3 = fmaf(sh[3][e], w, s3);
    }
    g_xc[(abase+0)*128+tid]=s0;
    g_xc[(abase+1)*128+tid]=s1;
    g_xc[(abase+2)*128+tid]=s2;
    g_xc[(abase+3)*128+tid]=s3;
}

// ---------------- per-agent kernel: post(t-1) + embed + LSTM(t) + A'/B'(t) ---------
__global__ __launch_bounds__(256, 1)
void k_agent(int t,
             const float* __restrict__ eps,
             const float* __restrict__ W_in,
             const float* __restrict__ b_ih, const float* __restrict__ b_hh,
             const float* __restrict__ W_l2p, const float* __restrict__ b_l2p,
             const float* __restrict__ W1,
             float* __restrict__ out)
{
    __shared__ float sh_hold[4][64];
    __shared__ __align__(16) float sh_hT[64*4];
    __shared__ float sh_ctx[4][64];
    __shared__ float sh_pos[4][2];
    __shared__ __align__(16) float sh_xT[128*4];
    __shared__ float sh_hnew[4][64];
    __shared__ float buf[1024];

    const int tid = threadIdx.x;
    const int abase = blockIdx.x*4;

    {
        int a = tid>>6, d = tid&63;
        int gi = (abase+a)*64+d;
        float hv = g_h[gi];
        sh_hold[a][d] = hv;
        sh_hT[d*4+a]  = hv;
        sh_ctx [a][d] = g_ctx[gi];
    }
    __syncthreads();

    if (t > 0){
        int tp = t-1;
        if (tid < 16){
            int a = tid>>2, o = tid&3;
            int f = o & 1; int lv = o>>1;
            const float* hh = &sh_hold[a][lv?32:0];
            float s = b_l2p[f];
            #pragma unroll 8
            for (int d=0; d<32; d++) s = fmaf(hh[d], W_l2p[d*2+f], s);
            #pragma unroll 8
            for (int k=0; k<64; k++) s = fmaf(sh_ctx[a][k], W_l2p[(32+k)*2+f], s);
            int i = abase+a;
            out[(lv?2:1)*(TT*NP*2) + tp*NP*2 + i*2 + f] = s;
            buf[a*4+o] = s;
        }
        __syncthreads();
        if (tid < 8){
            int a = tid>>1, f = tid&1; int i = abase+a;
            float mu = buf[a*4+f], lvv = buf[a*4+2+f];
            float p = mu + eps[tp*NP*2 + i*2 + f]*expf(0.5f*lvv);
            out[tp*NP*2 + i*2 + f] = p;
            sh_pos[a][f] = p;
            g_pos[i*2+f] = p;
            g_cur[i*2+f] += p;
        }
        __syncthreads();
    } else {
        if (tid < 8){ int a = tid>>1, f = tid&1; sh_pos[a][f] = g_pos[(abase+a)*2+f]; }
        __syncthreads();
    }
    if (t == TT) return;

    {
        int u = tid & 127; int a0 = tid >> 7;
        float s0 = g_xc[(abase+a0  )*128+u];
        float s1 = g_xc[(abase+a0+2)*128+u];
        float w0 = W_in[u], w1 = W_in[128+u];
        s0 = fmaf(sh_pos[a0  ][0], w0, fmaf(sh_pos[a0  ][1], w1, s0));
        s1 = fmaf(sh_pos[a0+2][0], w0, fmaf(sh_pos[a0+2][1], w1, s1));
        float w8[8];
        #pragma unroll
        for (int kb=0;kb<8;kb++){
            #pragma unroll
            for (int r=0;r<8;r++) w8[r] = W_in[(98+kb*8+r)*128+u];
            #pragma unroll
            for (int r=0;r<8;r++){
                s0 = fmaf(sh_ctx[a0  ][kb*8+r], w8[r], s0);
                s1 = fmaf(sh_ctx[a0+2][kb*8+r], w8[r], s1);
            }
        }
        sh_xT[u*4 + a0    ] = fmaxf(s0,0.f);
        sh_xT[u*4 + a0 + 2] = fmaxf(s1,0.f);
    }
    __syncthreads();

    {
        float binit = b_ih[tid] + b_hh[tid];
        ull acc01 = f32x2_dup(binit);
        ull acc23 = acc01;
        float w8[8];
        #pragma unroll
        for (int vb=0; vb<16; vb++){
            #pragma unroll
            for (int r=0;r<8;r++) w8[r] = g_WihT[(vb*8+r)*256+tid];
            #pragma unroll
            for (int r=0;r<8;r++){
                ulonglong2 xv = *(const ulonglong2*)(sh_xT + (vb*8+r)*4);
                ull wd = f32x2_dup(w8[r]);
                acc01 = f32x2_fma(xv.x, wd, acc01);
                acc23 = f32x2_fma(xv.y, wd, acc23);
            }
        }
        #pragma unroll
        for (int vb=0; vb<8; vb++){
            #pragma unroll
            for (int r=0;r<8;r++) w8[r] = g_WhhT[(vb*8+r)*256+tid];
            #pragma unroll
            for (int r=0;r<8;r++){
                ulonglong2 hv = *(const ulonglong2*)(sh_hT + (vb*8+r)*4);
                ull wd = f32x2_dup(w8[r]);
                acc01 = f32x2_fma(hv.x, wd, acc01);
                acc23 = f32x2_fma(hv.y, wd, acc23);
            }
        }
        float a0,a1,a2,a3;
        UNPACK2(a0,a1,acc01);
        UNPACK2(a2,a3,acc23);
        buf[0*256+tid]=a0; buf[1*256+tid]=a1; buf[2*256+tid]=a2; buf[3*256+tid]=a3;
    }
    __syncthreads();

    {
        int a = tid>>6, d = tid&63; int i = abase+a;
        float ig = buf[a*256 +   0 + d];
        float fg = buf[a*256 +  64 + d];
        float gg = buf[a*256 + 128 + d];
        float og = buf[a*256 + 192 + d];
        float co = g_c[i*64+d];
        float cn = sigmf(fg)*co + sigmf(ig)*tanhf(gg);
        float hn = sigmf(og)*tanhf(cn);
        g_c[i*64+d] = cn;
        g_h[i*64+d] = hn;
        sh_hnew[a][d] = hn;
    }
    __syncthreads();

    {
        int m = tid & 63; int w = (tid>>6)&1; int ah = tid>>7;
        float s0 = w ? g_bc[m] : 0.f; float s1 = s0;
        const float* Wp = W1 + (32 + w*64)*64 + m;
        float w8[8];
        #pragma unroll
        for (int db=0; db<8; db++){
            #pragma unroll
            for (int r=0;r<8;r++) w8[r] = Wp[(db*8+r)*64];
            #pragma unroll
            for (int r=0;r<8;r++){
                s0 = fmaf(sh_hnew[ah  ][db*8+r], w8[r], s0);
                s1 = fmaf(sh_hnew[ah+2][db*8+r], w8[r], s1);
            }
        }
        float m0 = g_M[m], m1 = g_M[64+m];
        float sg = w ? 1.f : -1.f;
        float cx0 = g_cur[(abase+ah  )*2], cy0 = g_cur[(abase+ah  )*2+1];
        float cx1 = g_cur[(abase+ah+2)*2], cy1 = g_cur[(abase+ah+2)*2+1];
        s0 = fmaf(sg*cx0, m0, fmaf(sg*cy0, m1, s0));
        s1 = fmaf(sg*cx1, m0, fmaf(sg*cy1, m1, s1));
        float* dst = w ? g_B : g_A;
        dst[(abase+ah  )*64+m] = s0;
        dst[(abase+ah+2)*64+m] = s1;
    }
}

// ---------------- pooling kernel: HMMA bf16 3-pass split GEMM -----------------------
// 512 blocks (1 row i), 256 threads (8 warps). Tile 128p x 64m.
// stage 1: gather + relu(A'+B') + bf16 hi/lo split into padded smem (stride 72 bf16).
// stage 2: per warp, 16-row p-slab: mma.sync m16n8k16, D = hh + hl + lh, fp32 accum.
// dynamic smem layout (bytes):
#define HHI    0        // 18432 : h_hi  [128][72] bf16
#define HLO    18432    // 18432 : h_lo
#define WHI    36864    //  9216 : W2_hi [64][72] bf16
#define WLO    46080    //  9216 : W2_lo
#define JIDXO  55296    //  2048 : compacted j indices
#define REDO   57344    //  2048 : cross-warp reduce [8][64] f32
#define CNTO   59392
#define POOL_SMEM 59424

__global__ __launch_bounds__(256, 2)
void k_pool(int t, const int* __restrict__ nei, const float* __restrict__ b2)
{
    extern __shared__ __align__(16) char smem[];
    const int tid = threadIdx.x, lane = tid & 31, wid = tid >> 5;
    const int i = blockIdx.x;
    const uint32_t sb = smem_to_u32(smem);
    int* jidx = (int*)(smem + JIDXO);

    if (tid == 0) *(int*)(smem + CNTO) = 0;

    // stage W2 hi/lo into padded smem: [m][stride 72], u32 pair copies
    {
        const uint32_t* whi = (const uint32_t*)g_W2hi;
        const uint32_t* wlo = (const uint32_t*)g_W2lo;
        #pragma unroll
        for (int r=0;r<8;r++){
            int idx = r*256 + tid;            // 2048 u32 pairs
            int m = idx >> 5, k2 = idx & 31;
            uint32_t off = (uint32_t)(m*72 + k2*2) * 2u;
            *(uint32_t*)(smem + WHI + off) = whi[m*32 + k2];
            *(uint32_t*)(smem + WLO + off) = wlo[m*32 + k2];
        }
    }

    // ---- compact valid neighbor indices (max is commutative; order irrelevant) ----
    {
        const int* row = nei + (long)t*NP*NP + (long)i*NP;
        int* pc = (int*)(smem + CNTO);
        // note: pc write by tid0 above is pre-sync; ballot segments use atomics after sync
        __syncthreads();
        #pragma unroll
        for (int c=0;c<2;c++){
            int j = c*256 + tid;
            int v = row[j] > 0;
            unsigned bal = __ballot_sync(0xFFFFFFFFu, v);
            int base = 0;
            if (lane == 0) base = atomicAdd(pc, __popc(bal));
            base = __shfl_sync(0xFFFFFFFFu, base, 0);
            if (v) jidx[base + __popc(bal & ((1u<<lane)-1u))] = j;
        }
    }
    __syncthreads();
    const int cnt = *(int*)(smem + CNTO);
    const int ntiles = (cnt + 127) >> 7;

    // stage-1 per-thread constants: m-pair and Bi pair
    const int m2 = lane;                       // 0..31 (m-pair index)
    const float2 Bi2 = *(const float2*)(g_B + i*64 + m2*2);

    // epilogue per-thread constants: b2 pairs for each n-chunk
    float2 b2v[8];
    #pragma unroll
    for (int nc=0;nc<8;nc++) b2v[nc] = *(const float2*)(b2 + nc*8 + (lane&3)*2);

    float cacc[8][4];
    #pragma unroll
    for (int nc=0;nc<8;nc++){
        #pragma unroll
        for (int c=0;c<4;c++) cacc[nc][c] = 0.f;
    }

    for (int jt=0; jt<ntiles; jt++){
        __syncthreads();                       // prev tile's ldmatrix reads done

        // stage 1: warp w fills rows p = it*8 + w; lanes span m (coalesced LDG.64)
        #pragma unroll
        for (int it=0; it<16; it++){
            int p = it*8 + wid;
            int gp = jt*128 + p;
            int j = jidx[(gp < cnt) ? gp : 0];
            float2 a = *(const float2*)(g_A + j*64 + m2*2);
            float v0 = fmaxf(a.x + Bi2.x, 0.f);
            float v1 = fmaxf(a.y + Bi2.y, 0.f);
            __nv_bfloat162 h = __floats2bfloat162_rn(v0, v1);
            float r0 = v0 - __bfloat162float(h.x);
            float r1 = v1 - __bfloat162float(h.y);
            __nv_bfloat162 l = __floats2bfloat162_rn(r0, r1);
            uint32_t off = (uint32_t)(p*72 + m2*2) * 2u;
            *(__nv_bfloat162*)(smem + HHI + off) = h;
            *(__nv_bfloat162*)(smem + HLO + off) = l;
        }
        __syncthreads();

        // stage 2: warp-level HMMA, 3 split passes accumulated in fp32 D
        float d[8][4];
        #pragma unroll
        for (int nc=0;nc<8;nc++){
            #pragma unroll
            for (int c=0;c<4;c++) d[nc][c] = 0.f;
        }
        {
            const int wslab = wid * 16;
            const uint32_t arow = (uint32_t)(wslab + (lane & 15));
            const uint32_t acol = (uint32_t)((lane >> 4) * 8);
            const uint32_t brow = (uint32_t)(lane & 15);
            #pragma unroll
            for (int mc=0; mc<4; mc++){
                uint32_t ahoff = (arow*72 + mc*16 + acol) * 2u;
                uint32_t ah[4], al[4];
                ldsm_x4(ah, sb + HHI + ahoff);
                ldsm_x4(al, sb + HLO + ahoff);
                #pragma unroll
                for (int nc=0; nc<8; nc++){
                    uint32_t boff = ((mc*16 + brow)*72 + nc*8) * 2u;
                    uint32_t bh[2], bl[2];
                    ldsm_x2t(bh, sb + WHI + boff);
                    ldsm_x2t(bl, sb + WLO + boff);
                    mma16816(d[nc], ah, bh);
                    mma16816(d[nc], ah, bl);
                    mma16816(d[nc], al, bh);
                }
            }
        }

        // epilogue: masked max into cacc (D m16n8 layout: rows lane>>2 and +8)
        {
            int p0 = wid*16 + (lane >> 2);
            bool ok0 = (jt*128 + p0    ) < cnt;
            bool ok1 = (jt*128 + p0 + 8) < cnt;
            #pragma unroll
            for (int nc=0;nc<8;nc++){
                if (ok0){
                    cacc[nc][0] = fmaxf(cacc[nc][0], d[nc][0] + b2v[nc].x);
                    cacc[nc][1] = fmaxf(cacc[nc][1], d[nc][1] + b2v[nc].y);
                }
                if (ok1){
                    cacc[nc][2] = fmaxf(cacc[nc][2], d[nc][2] + b2v[nc].x);
                    cacc[nc][3] = fmaxf(cacc[nc][3], d[nc][3] + b2v[nc].y);
                }
            }
        }
    }

    // ---- reduce: fold rows, shfl across row-groups, then cross-warp in smem --------
    float* red = (float*)(smem + REDO);
    #pragma unroll
    for (int nc=0;nc<8;nc++){
        float v0 = fmaxf(cacc[nc][0], cacc[nc][2]);
        float v1 = fmaxf(cacc[nc][1], cacc[nc][3]);
        #pragma unroll
        for (int off=16; off>=4; off>>=1){
            v0 = fmaxf(v0, __shfl_xor_sync(0xFFFFFFFFu, v0, off));
            v1 = fmaxf(v1, __shfl_xor_sync(0xFFFFFFFFu, v1, off));
        }
        if ((lane >> 2) == 0){
            red[wid*64 + nc*8 + lane*2    ] = v0;
            red[wid*64 + nc*8 + lane*2 + 1] = v1;
        }
    }
    __syncthreads();
    if (tid < 64){
        float v = red[tid];
        #pragma unroll
        for (int w=1; w<8; w++) v = fmaxf(v, red[w*64 + tid]);
        g_ctx[i*64 + tid] = v;
    }
}

// ---------------- launch ------------------------------------------------------------
extern "C" void kernel_launch(void* const* d_in, const int* in_sizes, int n_in,
                              void* d_out, int out_size)
{
    const float* last_pos = (const float*)d_in[0];
    const float* c_in     = (const float*)d_in[1];
    const float* z        = (const float*)d_in[2];
    const float* obs      = (const float*)d_in[3];
    const int*   nei      = (const int*)  d_in[4];
    // d_in[5] nei_num_index: unused by reference
    const float* h0       = (const float*)d_in[6];
    const float* c0       = (const float*)d_in[7];
    const float* eps      = (const float*)d_in[8];
    const float* W_in     = (const float*)d_in[9];
    const float* b_in     = (const float*)d_in[10];
    const float* W_ih     = (const float*)d_in[11];
    const float* W_hh     = (const float*)d_in[12];
    const float* b_ih     = (const float*)d_in[13];
    const float* b_hh     = (const float*)d_in[14];
    const float* W_l2p    = (const float*)d_in[15];
    const float* b_l2p    = (const float*)d_in[16];
    const float* W_sp     = (const float*)d_in[17];
    const float* b_sp     = (const float*)d_in[18];
    const float* W1       = (const float*)d_in[19];
    const float* b1       = (const float*)d_in[20];
    const float* W2       = (const float*)d_in[21];
    const float* b2       = (const float*)d_in[22];
    float* out = (float*)d_out;

    cudaFuncSetAttribute(k_pool, cudaFuncAttributeMaxDynamicSharedMemorySize, POOL_SMEM);

    k_init<<<128, 256>>>(last_pos, obs, h0, c0, W_sp, b_sp, W1, b1, W_ih, W_hh, W2);
    k_xc<<<128, 128>>>(c_in, z, W_in, b_in);

    for (int t=0; t<TT; t++){
        k_agent<<<128, 256>>>(t, eps, W_in, b_ih, b_hh, W_l2p, b_l2p, W1, out);
        k_pool<<<512, 256, POOL_SMEM>>>(t, nei, b2);
    }
    // final post (outputs for t = 11)
    k_agent<<<128, 256>>>(TT, eps, W_in, b_ih, b_hh, W_l2p, b_l2p, W1, out);
}